// round 16
// baseline (speedup 1.0000x reference)
#include <cuda_runtime.h>

#define FULLMASK 0xffffffffu

// Parent ids packed 5 bits each: LO holds joints 1..12, HI holds 13..23.
// PARENT = [-,0,0,0,1,2,3,4,5,6,7,8,9,9,9,12,13,14,16,17,18,19,20,21]
#define PAR_LO 0x04A0E62906208000ULL
#define PAR_HI 0x0056939460E6B129ULL

__device__ __forceinline__ void axisang_rot(float x, float y, float z, float* __restrict__ R) {
    // reference: theta = sqrt(dot + 1e-8); R = I + s*K + (1-c)*K^2
    // fast-math: MUFU.RSQ / MUFU.SIN / MUFU.COS (error ~2^-21, budget 1e-3)
    float t2 = x * x + y * y + z * z + 1e-8f;
    float inv = rsqrtf(t2);
    float th = t2 * inv;            // sqrt(t2)
    float ax = x * inv, ay = y * inv, az = z * inv;
    float s = __sinf(th);
    float c = __cosf(th);
    float oc = 1.0f - c;
    float xx = ax * ax, yy = ay * ay, zz = az * az;
    float xy = ax * ay, xz = ax * az, yz = ay * az;
    R[0] = 1.0f + oc * (-zz - yy);
    R[1] = -s * az + oc * xy;
    R[2] =  s * ay + oc * xz;
    R[3] =  s * az + oc * xy;
    R[4] = 1.0f + oc * (-zz - xx);
    R[5] = -s * ax + oc * yz;
    R[6] = -s * ay + oc * xz;
    R[7] =  s * ax + oc * yz;
    R[8] = 1.0f + oc * (-yy - xx);
}

// ---------------------------------------------------------------------------
// Joint-parallel kernel: one warp per element, lane j (<24) owns joint j.
// Kinematic chain = prefix product over depth-8 tree via 4 pointer-jumping
// rounds of warp shuffles. No shared memory; all per-lane state in ~64 regs.
// l2w/skts stored as direct lane-owned float4 rows (warp-contiguous 1536B).
// ---------------------------------------------------------------------------
__global__ void __launch_bounds__(256)
kin_kernel(const float* __restrict__ pelvis, const float* __restrict__ bones,
           const float* __restrict__ rest, const int* __restrict__ idxs,
           float* __restrict__ out, int B)
{
    const int lane = threadIdx.x & 31;
    const int e = blockIdx.x * 8 + (threadIdx.x >> 5);
    if (e >= B) return;
    const bool alive = (lane < 24);
    const int j = alive ? lane : 23;   // lanes 24-31 shadow joint 23 (masked stores)

    const int idx = __ldg(idxs + e);

    const float px = __ldg(pelvis + (size_t)idx * 3 + 0);
    const float py = __ldg(pelvis + (size_t)idx * 3 + 1);
    const float pz = __ldg(pelvis + (size_t)idx * 3 + 2);

    // parent id from packed immediates (root gets -1)
    int p;
    if (j == 0) p = -1;
    else p = (int)(((j < 13) ? (PAR_LO >> (5 * (j - 1)))
                             : (PAR_HI >> (5 * (j - 13)))) & 31ULL);

    // bone vector (coalesced: warp reads 288B contiguous) + rotation
    const float* bp = bones + (size_t)idx * 72 + j * 3;
    const float vx = __ldg(bp + 0), vy = __ldg(bp + 1), vz = __ldg(bp + 2);
    float R[9];
    axisang_rot(vx, vy, vz, R);

    const size_t Bs = (size_t)B;
    // early outputs: rots + bone passthrough (R not needed afterwards)
    if (alive) {
        float* ro = out + Bs * 912 + (size_t)e * 216 + j * 9;
#pragma unroll
        for (int m = 0; m < 9; ++m) ro[m] = R[m];
        float* bo = out + Bs * 72 + (size_t)e * 72 + j * 3;
        bo[0] = vx; bo[1] = vy; bo[2] = vz;
    }

    // relative translation
    float tx, ty, tz;
    if (j == 0) {
        tx = __ldg(rest + 0); ty = __ldg(rest + 1); tz = __ldg(rest + 2);
    } else {
        tx = __ldg(rest + 3 * j + 0) - __ldg(rest + 3 * p + 0);
        ty = __ldg(rest + 3 * j + 1) - __ldg(rest + 3 * p + 1);
        tz = __ldg(rest + 3 * j + 2) - __ldg(rest + 3 * p + 2);
    }

    // local transform rows: T[r*4+c], col 3 = translation
    float T[12] = { R[0], R[1], R[2], tx,
                    R[3], R[4], R[5], ty,
                    R[6], R[7], R[8], tz };

    // 4 pointer-jumping rounds: covers depth <= 8 (max depth of joint 23)
#pragma unroll
    for (int r = 0; r < 4; ++r) {
        const int src = (p < 0) ? 0 : p;
        float Tp[12];
#pragma unroll
        for (int k = 0; k < 12; ++k) Tp[k] = __shfl_sync(FULLMASK, T[k], src);
        const int pp = __shfl_sync(FULLMASK, p, src);
        if (p >= 0) {
            float N[12];
#pragma unroll
            for (int rr = 0; rr < 3; ++rr) {
                N[rr*4+0] = Tp[rr*4+0]*T[0] + Tp[rr*4+1]*T[4] + Tp[rr*4+2]*T[8];
                N[rr*4+1] = Tp[rr*4+0]*T[1] + Tp[rr*4+1]*T[5] + Tp[rr*4+2]*T[9];
                N[rr*4+2] = Tp[rr*4+0]*T[2] + Tp[rr*4+1]*T[6] + Tp[rr*4+2]*T[10];
                N[rr*4+3] = Tp[rr*4+0]*T[3] + Tp[rr*4+1]*T[7] + Tp[rr*4+2]*T[11]
                          + Tp[rr*4+3];
            }
#pragma unroll
            for (int k = 0; k < 12; ++k) T[k] = N[k];
            p = pp;
        }
    }

    // world translation (pelvis folded in)
    const float twx = T[3]  + px;
    const float twy = T[7]  + py;
    const float twz = T[11] + pz;

    if (alive) {
        // l2w: 4 x float4 rows, lane-owned 64B block (warp: contiguous 1536B)
        float4* l4 = reinterpret_cast<float4*>(
            out + Bs * 528 + (size_t)e * 384 + j * 16);
        l4[0] = make_float4(T[0], T[1], T[2],  twx);
        l4[1] = make_float4(T[4], T[5], T[6],  twy);
        l4[2] = make_float4(T[8], T[9], T[10], twz);
        l4[3] = make_float4(0.f, 0.f, 0.f, 1.f);

        // skts: rigid inverse [R^T | -R^T tw] (rotation chain => orthogonal)
        const float itx = -(T[0]*twx + T[4]*twy + T[8]*twz);
        const float ity = -(T[1]*twx + T[5]*twy + T[9]*twz);
        const float itz = -(T[2]*twx + T[6]*twy + T[10]*twz);
        float4* s4 = reinterpret_cast<float4*>(
            out + Bs * 144 + (size_t)e * 384 + j * 16);
        s4[0] = make_float4(T[0], T[4], T[8],  itx);
        s4[1] = make_float4(T[1], T[5], T[9],  ity);
        s4[2] = make_float4(T[2], T[6], T[10], itz);
        s4[3] = make_float4(0.f, 0.f, 0.f, 1.f);

        // kp
        float* kq = out + (size_t)e * 72 + j * 3;
        kq[0] = twx; kq[1] = twy; kq[2] = twz;
    }
}

extern "C" void kernel_launch(void* const* d_in, const int* in_sizes, int n_in,
                              void* d_out, int out_size)
{
    const float* pelvis = (const float*)d_in[0];
    const float* bones  = (const float*)d_in[1];
    const float* rest   = (const float*)d_in[2];
    const int*   idxs   = (const int*)d_in[3];
    const int B = in_sizes[3];
    float* out = (float*)d_out;

    // one warp per element, 8 warps per block
    int blocks = (B + 7) / 8;
    kin_kernel<<<blocks, 256>>>(pelvis, bones, rest, idxs, out, B);
}

// round 17
// speedup vs baseline: 1.3548x; 1.3548x over previous
#include <cuda_runtime.h>

#define FULLMASK 0xffffffffu

// Parent ids packed 5 bits each: LO holds joints 1..12, HI holds 13..23.
// PARENT = [-,0,0,0,1,2,3,4,5,6,7,8,9,9,9,12,13,14,16,17,18,19,20,21]
#define PAR_LO 0x04A0E62906208000ULL
#define PAR_HI 0x0056939460E6B129ULL

__device__ __forceinline__ void axisang_rot(float x, float y, float z, float* __restrict__ R) {
    // reference: theta = sqrt(dot + 1e-8); R = I + s*K + (1-c)*K^2
    // fast-math: MUFU.RSQ / MUFU.SIN / MUFU.COS (error ~2^-21, budget 1e-3)
    float t2 = x * x + y * y + z * z + 1e-8f;
    float inv = rsqrtf(t2);
    float th = t2 * inv;            // sqrt(t2)
    float ax = x * inv, ay = y * inv, az = z * inv;
    float s = __sinf(th);
    float c = __cosf(th);
    float oc = 1.0f - c;
    float xx = ax * ax, yy = ay * ay, zz = az * az;
    float xy = ax * ay, xz = ax * az, yz = ay * az;
    R[0] = 1.0f + oc * (-zz - yy);
    R[1] = -s * az + oc * xy;
    R[2] =  s * ay + oc * xz;
    R[3] =  s * az + oc * xy;
    R[4] = 1.0f + oc * (-zz - xx);
    R[5] = -s * ax + oc * yz;
    R[6] = -s * ay + oc * xz;
    R[7] =  s * ax + oc * yz;
    R[8] = 1.0f + oc * (-yy - xx);
}

// ---------------------------------------------------------------------------
// Joint-parallel kernel: one warp per element, lane j (<24) owns joint j.
// Chain = prefix product over depth-8 tree via 4 pointer-jumping shuffle
// rounds. l2w/skts stored directly as lane-owned float4 rows (contiguous).
// Small outputs (rots/bone/kp) staged in 1.4KB/warp smem, flushed as fully
// coalesced float4 stores (fixes R16's L1-wavefront bottleneck).
// Smem float4 map: rots words [0,216) = f4 [0,54); bone [216,288) = f4 [54,72);
// kp [288,360) = f4 [72,90).
// ---------------------------------------------------------------------------
__global__ void __launch_bounds__(256)
kin_kernel(const float* __restrict__ pelvis, const float* __restrict__ bones,
           const float* __restrict__ rest, const int* __restrict__ idxs,
           float* __restrict__ out, int B)
{
    __shared__ float sb[8][368];    // 360 used + pad
    const int lane = threadIdx.x & 31;
    const int wid  = threadIdx.x >> 5;
    float* SB = sb[wid];
    const int e = blockIdx.x * 8 + wid;
    if (e >= B) return;
    const bool alive = (lane < 24);
    const int j = alive ? lane : 23;   // lanes 24-31 shadow joint 23 (masked stores)

    const int idx = __ldg(idxs + e);

    const float px = __ldg(pelvis + (size_t)idx * 3 + 0);
    const float py = __ldg(pelvis + (size_t)idx * 3 + 1);
    const float pz = __ldg(pelvis + (size_t)idx * 3 + 2);

    // parent id from packed immediates (root gets -1)
    int p;
    if (j == 0) p = -1;
    else p = (int)(((j < 13) ? (PAR_LO >> (5 * (j - 1)))
                             : (PAR_HI >> (5 * (j - 13)))) & 31ULL);

    // bone vector (coalesced: warp reads 288B contiguous) + rotation
    const float* bp = bones + (size_t)idx * 72 + j * 3;
    const float vx = __ldg(bp + 0), vy = __ldg(bp + 1), vz = __ldg(bp + 2);
    float R[9];
    axisang_rot(vx, vy, vz, R);

    // stage rots + bone passthrough into smem (lane-owned slots)
    if (alive) {
        float* rq = SB + j * 9;
#pragma unroll
        for (int m = 0; m < 9; ++m) rq[m] = R[m];
        float* bq = SB + 216 + j * 3;
        bq[0] = vx; bq[1] = vy; bq[2] = vz;
    }

    // relative translation
    float tx, ty, tz;
    if (j == 0) {
        tx = __ldg(rest + 0); ty = __ldg(rest + 1); tz = __ldg(rest + 2);
    } else {
        tx = __ldg(rest + 3 * j + 0) - __ldg(rest + 3 * p + 0);
        ty = __ldg(rest + 3 * j + 1) - __ldg(rest + 3 * p + 1);
        tz = __ldg(rest + 3 * j + 2) - __ldg(rest + 3 * p + 2);
    }

    // local transform rows: T[r*4+c], col 3 = translation
    float T[12] = { R[0], R[1], R[2], tx,
                    R[3], R[4], R[5], ty,
                    R[6], R[7], R[8], tz };

    // 4 pointer-jumping rounds: covers depth <= 8 (max depth of joint 23)
#pragma unroll
    for (int r = 0; r < 4; ++r) {
        const int src = (p < 0) ? 0 : p;
        float Tp[12];
#pragma unroll
        for (int k = 0; k < 12; ++k) Tp[k] = __shfl_sync(FULLMASK, T[k], src);
        const int pp = __shfl_sync(FULLMASK, p, src);
        if (p >= 0) {
            float N[12];
#pragma unroll
            for (int rr = 0; rr < 3; ++rr) {
                N[rr*4+0] = Tp[rr*4+0]*T[0] + Tp[rr*4+1]*T[4] + Tp[rr*4+2]*T[8];
                N[rr*4+1] = Tp[rr*4+0]*T[1] + Tp[rr*4+1]*T[5] + Tp[rr*4+2]*T[9];
                N[rr*4+2] = Tp[rr*4+0]*T[2] + Tp[rr*4+1]*T[6] + Tp[rr*4+2]*T[10];
                N[rr*4+3] = Tp[rr*4+0]*T[3] + Tp[rr*4+1]*T[7] + Tp[rr*4+2]*T[11]
                          + Tp[rr*4+3];
            }
#pragma unroll
            for (int k = 0; k < 12; ++k) T[k] = N[k];
            p = pp;
        }
    }

    // world translation (pelvis folded in)
    const float twx = T[3]  + px;
    const float twy = T[7]  + py;
    const float twz = T[11] + pz;

    const size_t Bs = (size_t)B;

    if (alive) {
        // l2w: 4 x float4 rows, lane-owned 64B block (warp: contiguous 1536B)
        float4* l4 = reinterpret_cast<float4*>(
            out + Bs * 528 + (size_t)e * 384 + j * 16);
        l4[0] = make_float4(T[0], T[1], T[2],  twx);
        l4[1] = make_float4(T[4], T[5], T[6],  twy);
        l4[2] = make_float4(T[8], T[9], T[10], twz);
        l4[3] = make_float4(0.f, 0.f, 0.f, 1.f);

        // skts: rigid inverse [R^T | -R^T tw] (rotation chain => orthogonal)
        const float itx = -(T[0]*twx + T[4]*twy + T[8]*twz);
        const float ity = -(T[1]*twx + T[5]*twy + T[9]*twz);
        const float itz = -(T[2]*twx + T[6]*twy + T[10]*twz);
        float4* s4 = reinterpret_cast<float4*>(
            out + Bs * 144 + (size_t)e * 384 + j * 16);
        s4[0] = make_float4(T[0], T[4], T[8],  itx);
        s4[1] = make_float4(T[1], T[5], T[9],  ity);
        s4[2] = make_float4(T[2], T[6], T[10], itz);
        s4[3] = make_float4(0.f, 0.f, 0.f, 1.f);

        // stage kp
        float* kq = SB + 288 + j * 3;
        kq[0] = twx; kq[1] = twy; kq[2] = twz;
    }

    __syncwarp();

    // ---- coalesced flush of staged small outputs ----
    const float4* sf4 = reinterpret_cast<const float4*>(SB);

    // rots: 54 float4 -> e*216 floats at out + Bs*912
    {
        float4* ro = reinterpret_cast<float4*>(out + Bs * 912 + (size_t)e * 216);
        if (lane < 32)            ro[lane] = sf4[lane];          // 0..31
        if (lane < 22)            ro[32 + lane] = sf4[32 + lane];// 32..53
    }
    // bone: 18 float4 -> e*72 floats at out + Bs*72
    if (lane < 18) {
        float4* bo = reinterpret_cast<float4*>(out + Bs * 72 + (size_t)e * 72);
        bo[lane] = sf4[54 + lane];
    }
    // kp: 18 float4 -> e*72 floats at out
    if (lane < 18) {
        float4* ko = reinterpret_cast<float4*>(out + (size_t)e * 72);
        ko[lane] = sf4[72 + lane];
    }
}

extern "C" void kernel_launch(void* const* d_in, const int* in_sizes, int n_in,
                              void* d_out, int out_size)
{
    const float* pelvis = (const float*)d_in[0];
    const float* bones  = (const float*)d_in[1];
    const float* rest   = (const float*)d_in[2];
    const int*   idxs   = (const int*)d_in[3];
    const int B = in_sizes[3];
    float* out = (float*)d_out;

    // one warp per element, 8 warps per block
    int blocks = (B + 7) / 8;
    kin_kernel<<<blocks, 256>>>(pelvis, bones, rest, idxs, out, B);
}